// round 11
// baseline (speedup 1.0000x reference)
#include <cuda_runtime.h>
#include <cuda_fp16.h>
#include <cstdint>

#define NODES_TOTAL 100000
#define NNODES      20000
#define TN          50
#define INF         256
#define HIDF        256
#define OUTF        256
#define CATF        512

// Scratch (static __device__ arrays: allocation-free per harness rules)
__device__ __align__(16) __half g_qh[(size_t)NODES_TOTAL * HIDF];  // 51.2 MB (L2-resident)
__device__ __align__(16) __half g_cat[(size_t)NNODES * CATF];      // 20.5 MB

// ---------------------------------------------------------------------------
// helpers
// ---------------------------------------------------------------------------
__device__ __forceinline__ void mma_f16_f32acc(float c[4], const uint32_t a[4],
                                               uint32_t b0, uint32_t b1) {
    asm volatile("mma.sync.aligned.m16n8k16.row.col.f32.f16.f16.f32 "
                 "{%0,%1,%2,%3}, {%4,%5,%6,%7}, {%8,%9}, {%0,%1,%2,%3};"
                 : "+f"(c[0]), "+f"(c[1]), "+f"(c[2]), "+f"(c[3])
                 : "r"(a[0]), "r"(a[1]), "r"(a[2]), "r"(a[3]), "r"(b0), "r"(b1));
}

__device__ __forceinline__ void ldmatrix_x4(uint32_t r[4], uint32_t saddr) {
    asm volatile("ldmatrix.sync.aligned.m8n8.x4.shared.b16 {%0,%1,%2,%3}, [%4];"
                 : "=r"(r[0]), "=r"(r[1]), "=r"(r[2]), "=r"(r[3]) : "r"(saddr));
}

__device__ __forceinline__ uint32_t pack_h2(float x, float y) {
    __half2 h = __float22half2_rn(make_float2(x, y));
    return *(uint32_t*)&h;
}

#define SROWH 40   // smem row stride in halves (80B -> conflict-free ldmatrix)

// ===========================================================================
// GEMM body (R9-proven): C[m0..m0+127, n0..n0+127] = relu(A@B^T + bias).
// 8 warps (64x32 each), K chunked by 32, double smem buffer, stage-after-
// compute (no prefetch regs), ONE __syncthreads per chunk.
// ===========================================================================
template <int NCHUNK, bool A_FP16, bool OUT_FP16>
__device__ __forceinline__ void gemm_body(
    const void* __restrict__ Av, const float* __restrict__ B,
    const float* __restrict__ bias, void* __restrict__ Cv, int M,
    int m0, int n0, __half* sAbuf, __half* sBbuf)
{
    const int tid  = threadIdx.x;
    const int warp = tid >> 5;
    const int lane = tid & 31;
    const int g    = lane >> 2;
    const int tg   = lane & 3;
    const int wm   = (warp >> 2) * 64;
    const int wn   = (warp & 3) * 32;
    const int K    = NCHUNK * 32;

    const int srow = tid >> 1;
    const int part = (tid & 1) * 16;
    const bool va  = (m0 + srow) < M;

    const float*  A32 = (const float*)Av;
    const __half* A16 = (const __half*)Av;

    float acc[4][4][4];
    #pragma unroll
    for (int i = 0; i < 4; i++)
        #pragma unroll
        for (int j = 0; j < 4; j++)
            #pragma unroll
            for (int r = 0; r < 4; r++) acc[i][j][r] = 0.f;

    // ---- stage chunk 0 into buffer 0 ----
    #pragma unroll
    for (int i = 0; i < 4; i++) {
        const int kc = part + i * 4;
        uint2 apk;
        if (A_FP16) {
            apk = va ? *(const uint2*)(A16 + (size_t)(m0 + srow) * K + kc)
                     : make_uint2(0u, 0u);
        } else {
            float4 v = va ? *(const float4*)(A32 + (size_t)(m0 + srow) * K + kc)
                          : make_float4(0.f, 0.f, 0.f, 0.f);
            apk = make_uint2(pack_h2(v.x, v.y), pack_h2(v.z, v.w));
        }
        *(uint2*)&sAbuf[srow * SROWH + kc] = apk;
        float4 vb = *(const float4*)(B + (size_t)(n0 + srow) * K + kc);
        *(uint2*)&sBbuf[srow * SROWH + kc] =
            make_uint2(pack_h2(vb.x, vb.y), pack_h2(vb.z, vb.w));
    }
    __syncthreads();

    const uint32_t uA0 = (uint32_t)__cvta_generic_to_shared(sAbuf);
    const uint32_t uA1 = uA0 + 128 * SROWH * 2;
    const uint32_t uB0 = (uint32_t)__cvta_generic_to_shared(sBbuf);
    const uint32_t uB1 = uB0 + 128 * SROWH * 2;

    const uint32_t offA = (uint32_t)(((lane & 15) * SROWH + (lane >> 4) * 8) * 2);
    const uint32_t offB = (uint32_t)((((lane >> 4) * 8 + (lane & 7)) * SROWH
                                      + ((lane >> 3) & 1) * 8) * 2);

    #pragma unroll 1
    for (int c = 0; c < NCHUNK; c++) {
        const uint32_t ubA = (c & 1) ? uA1 : uA0;
        const uint32_t ubB = (c & 1) ? uB1 : uB0;
        #pragma unroll
        for (int ks = 0; ks < 2; ks++) {
            uint32_t af[4][4];
            #pragma unroll
            for (int mf = 0; mf < 4; mf++)
                ldmatrix_x4(af[mf], ubA + offA
                            + (uint32_t)(((wm + mf * 16) * SROWH + ks * 16) * 2));
            uint32_t bf[2][4];
            #pragma unroll
            for (int p = 0; p < 2; p++)
                ldmatrix_x4(bf[p], ubB + offB
                            + (uint32_t)(((wn + p * 16) * SROWH + ks * 16) * 2));
            #pragma unroll
            for (int mf = 0; mf < 4; mf++)
                #pragma unroll
                for (int nf = 0; nf < 4; nf++)
                    mma_f16_f32acc(acc[mf][nf], af[mf], bf[nf >> 1][(nf & 1) * 2],
                                   bf[nf >> 1][(nf & 1) * 2 + 1]);
        }

        // stage chunk c+1 into the other buffer (safe: its readers drained
        // before the sync that ended the previous chunk)
        if (c + 1 < NCHUNK) {
            const int kk = (c + 1) * 32 + part;
            __half* dA = (__half*)(((c + 1) & 1) ? (sAbuf + 128 * SROWH) : sAbuf);
            __half* dB = (__half*)(((c + 1) & 1) ? (sBbuf + 128 * SROWH) : sBbuf);
            #pragma unroll
            for (int i = 0; i < 4; i++) {
                uint2 apk;
                if (A_FP16) {
                    apk = va ? *(const uint2*)(A16 + (size_t)(m0 + srow) * K + kk + i * 4)
                             : make_uint2(0u, 0u);
                } else {
                    float4 v = va ? *(const float4*)(A32 + (size_t)(m0 + srow) * K + kk + i * 4)
                                  : make_float4(0.f, 0.f, 0.f, 0.f);
                    apk = make_uint2(pack_h2(v.x, v.y), pack_h2(v.z, v.w));
                }
                *(uint2*)&dA[srow * SROWH + part + i * 4] = apk;
                float4 vb = *(const float4*)(B + (size_t)(n0 + srow) * K + kk + i * 4);
                *(uint2*)&dB[srow * SROWH + part + i * 4] =
                    make_uint2(pack_h2(vb.x, vb.y), pack_h2(vb.z, vb.w));
            }
        }
        __syncthreads();
    }

    // ---- epilogue: bias + relu, store (C row stride 256 elements) ----
    #pragma unroll
    for (int mf = 0; mf < 4; mf++) {
        #pragma unroll
        for (int half = 0; half < 2; half++) {
            const int m = m0 + wm + mf * 16 + g + half * 8;
            if (m < M) {
                #pragma unroll
                for (int nf = 0; nf < 4; nf++) {
                    const int cc = n0 + wn + nf * 8 + tg * 2;
                    const float v0 = fmaxf(acc[mf][nf][half * 2 + 0] + __ldg(&bias[cc]),     0.f);
                    const float v1 = fmaxf(acc[mf][nf][half * 2 + 1] + __ldg(&bias[cc + 1]), 0.f);
                    if (OUT_FP16) {
                        const uint32_t p = pack_h2(v0, v1);
                        *(uint32_t*)((__half*)Cv + (size_t)m * 256 + cc) = p;
                    } else {
                        *(float2*)((float*)Cv + (size_t)m * 256 + cc) = make_float2(v0, v1);
                    }
                }
            }
        }
    }
}

// ===========================================================================
// Agg half-column body: h_agg[n, colOff..colOff+127] (4 cols/lane, uint2
// loads). Optionally also copies h[nodeset[n]] (fp32->fp16) into the self
// half of the concat row. Column-separable: needs only QH[:, colOff..+127].
// ===========================================================================
__device__ __forceinline__ void agg_half_body(
    int n, int warp, int lane,
    const float* __restrict__ h, const int* __restrict__ nodeset,
    const int* __restrict__ nb_nodes, const float* __restrict__ nb_w,
    int colOff, bool doSelf, int (*s_idx)[TN], float (*s_w)[TN])
{
    for (int j = lane; j < TN; j += 32) {
        s_idx[warp][j] = nb_nodes[n * TN + j];
        s_w[warp][j]   = nb_w[n * TN + j];
    }
    __syncwarp();

    float wsum = 0.f;
    #pragma unroll
    for (int t = 0; t < TN; t++) wsum += s_w[warp][t];

    const int colb = colOff + lane * 4;   // 4 half columns per lane
    float acc[4] = {0.f, 0.f, 0.f, 0.f};

    #pragma unroll 10
    for (int t = 0; t < TN; t++) {
        const int   idx = s_idx[warp][t];
        const float w   = s_w[warp][t];
        union { uint2 u; __half2 h2[2]; } q;
        q.u = *(const uint2*)(g_qh + (size_t)idx * HIDF + colb);
        const float2 f0 = __half22float2(q.h2[0]);
        const float2 f1 = __half22float2(q.h2[1]);
        acc[0] += w * f0.x; acc[1] += w * f0.y;
        acc[2] += w * f1.x; acc[3] += w * f1.y;
    }
    const float inv = 1.f / wsum;
    union { uint2 u; __half2 h2[2]; } o;
    o.h2[0] = __float22half2_rn(make_float2(acc[0] * inv, acc[1] * inv));
    o.h2[1] = __float22half2_rn(make_float2(acc[2] * inv, acc[3] * inv));
    *(uint2*)(g_cat + (size_t)n * CATF + INF + colb) = o.u;

    if (doSelf) {
        const int self = nodeset[n];
        const int cb   = lane * 8;
        const float4 s0 = *(const float4*)(h + (size_t)self * INF + cb);
        const float4 s1 = *(const float4*)(h + (size_t)self * INF + cb + 4);
        union { uint4 u; __half2 h2[4]; } sc;
        sc.h2[0] = __float22half2_rn(make_float2(s0.x, s0.y));
        sc.h2[1] = __float22half2_rn(make_float2(s0.z, s0.w));
        sc.h2[2] = __float22half2_rn(make_float2(s1.x, s1.y));
        sc.h2[3] = __float22half2_rn(make_float2(s1.z, s1.w));
        *(uint4*)(g_cat + (size_t)n * CATF + cb) = sc.u;
    }
}

// ===========================================================================
// k1 / k2: GEMM-A N-half, optionally fused with the agg blocks for the
// PREVIOUS N-half's columns (overlap: tensor-bound GEMM || L2-bound agg).
// Blocks [0, gemmBlocks): gemm rows blockIdx*128, fixed n0.
// Blocks [gemmBlocks, ...): agg for columns [aggColOff, aggColOff+128).
// ===========================================================================
__global__ __launch_bounds__(256, 2) void fused_gemmA_agg_kernel(
    const float* __restrict__ A, const float* __restrict__ B,
    const float* __restrict__ bias, __half* __restrict__ C, int M,
    int n0, int gemmBlocks,
    const float* __restrict__ h, const int* __restrict__ nodeset,
    const int* __restrict__ nb_nodes, const float* __restrict__ nb_w,
    int aggColOff)
{
    __shared__ __half sA[2][128 * SROWH];
    __shared__ __half sB[2][128 * SROWH];
    __shared__ int   s_idx[8][TN];
    __shared__ float s_w[8][TN];

    if ((int)blockIdx.x < gemmBlocks) {
        gemm_body<8, false, true>(A, B, bias, C, M,
                                  (int)blockIdx.x * 128, n0, &sA[0][0], &sB[0][0]);
    } else {
        const int blk  = (int)blockIdx.x - gemmBlocks;
        const int warp = threadIdx.x >> 5;
        const int lane = threadIdx.x & 31;
        const int n    = blk * 8 + warp;
        agg_half_body(n, warp, lane, h, nodeset, nb_nodes, nb_w,
                      aggColOff, false, s_idx, s_w);
    }
}

// k3: standalone high-occupancy agg for the second column half + self copy
__global__ __launch_bounds__(256) void agg_half2_kernel(
    const float* __restrict__ h, const int* __restrict__ nodeset,
    const int* __restrict__ nb_nodes, const float* __restrict__ nb_w)
{
    __shared__ int   s_idx[8][TN];
    __shared__ float s_w[8][TN];
    const int warp = threadIdx.x >> 5;
    const int lane = threadIdx.x & 31;
    const int n    = blockIdx.x * 8 + warp;
    agg_half_body(n, warp, lane, h, nodeset, nb_nodes, nb_w,
                  128, true, s_idx, s_w);
}

// k4: GEMM-C (paired-grid: colTile fastest so cat slab is L2-hot on 2nd tile)
__global__ __launch_bounds__(256, 2) void gemm_c_kernel(
    const __half* __restrict__ A, const float* __restrict__ B,
    const float* __restrict__ bias, float* __restrict__ C, int M)
{
    __shared__ __half sA[2][128 * SROWH];
    __shared__ __half sB[2][128 * SROWH];
    gemm_body<16, true, false>(A, B, bias, C, M,
                               (int)(blockIdx.x >> 1) * 128,
                               (int)(blockIdx.x & 1) * 128, &sA[0][0], &sB[0][0]);
}

// ---------------------------------------------------------------------------
// k5: in-place row L2 normalize of d_out [20000, 256]; one warp per row
// ---------------------------------------------------------------------------
__global__ __launch_bounds__(256) void norm_kernel(float* __restrict__ out)
{
    const int gwarp = (blockIdx.x * blockDim.x + threadIdx.x) >> 5;
    const int lane  = threadIdx.x & 31;
    if (gwarp >= NNODES) return;
    float* row = out + (size_t)gwarp * OUTF;

    float4 v0 = *(float4*)&row[lane * 4];
    float4 v1 = *(float4*)&row[128 + lane * 4];
    float ss = v0.x * v0.x + v0.y * v0.y + v0.z * v0.z + v0.w * v0.w
             + v1.x * v1.x + v1.y * v1.y + v1.z * v1.z + v1.w * v1.w;
    #pragma unroll
    for (int o = 16; o; o >>= 1) ss += __shfl_xor_sync(0xffffffffu, ss, o);
    const float inv = rsqrtf(ss);
    v0.x *= inv; v0.y *= inv; v0.z *= inv; v0.w *= inv;
    v1.x *= inv; v1.y *= inv; v1.z *= inv; v1.w *= inv;
    *(float4*)&row[lane * 4]       = v0;
    *(float4*)&row[128 + lane * 4] = v1;
}

// ---------------------------------------------------------------------------
extern "C" void kernel_launch(void* const* d_in, const int* in_sizes, int n_in,
                              void* d_out, int out_size)
{
    const float* h        = (const float*)d_in[0];
    const int*   nodeset  = (const int*)d_in[1];
    const int*   nb_nodes = (const int*)d_in[2];
    const float* nb_w     = (const float*)d_in[3];
    const float* Qw       = (const float*)d_in[4];
    const float* Qb       = (const float*)d_in[5];
    const float* Ww       = (const float*)d_in[6];
    const float* Wb       = (const float*)d_in[7];
    float*       out      = (float*)d_out;

    __half* qh  = nullptr;
    __half* cat = nullptr;
    cudaGetSymbolAddress((void**)&qh,  g_qh);
    cudaGetSymbolAddress((void**)&cat, g_cat);

    const int tilesA = (NODES_TOTAL + 127) / 128;   // 782
    const int aggBlk = NNODES / 8;                  // 2500

    // k1: QH cols 0..127 (all rows)
    fused_gemmA_agg_kernel<<<tilesA, 256>>>(
        h, Qw, Qb, qh, NODES_TOTAL, /*n0=*/0, /*gemmBlocks=*/tilesA,
        h, nodeset, nb_nodes, nb_w, /*aggColOff=*/0);

    // k2: QH cols 128..255  ||  agg of cols 0..127 (overlapped in one grid)
    fused_gemmA_agg_kernel<<<tilesA + aggBlk, 256>>>(
        h, Qw, Qb, qh, NODES_TOTAL, /*n0=*/128, /*gemmBlocks=*/tilesA,
        h, nodeset, nb_nodes, nb_w, /*aggColOff=*/0);

    // k3: agg of cols 128..255 + self-feature copy
    agg_half2_kernel<<<aggBlk, 256>>>(h, nodeset, nb_nodes, nb_w);

    // k4: out = relu(g_cat @ Ww^T + Wb)  [20000, 256], K=512
    {
        const int tilesM = (NNODES + 127) / 128;    // 157
        gemm_c_kernel<<<tilesM * 2, 256>>>(cat, Ww, Wb, out, NNODES);
    }
    // k5: in-place L2 normalize
    norm_kernel<<<(NNODES * 32 + 255) / 256, 256>>>(out);
}

// round 12
// speedup vs baseline: 2.1745x; 2.1745x over previous
#include <cuda_runtime.h>
#include <cuda_fp16.h>
#include <cstdint>

#define NODES_TOTAL 100000
#define NNODES      20000
#define TN          50
#define INF         256
#define HIDF        256
#define OUTF        256
#define CATF        512

// Scratch (static __device__ arrays: allocation-free per harness rules)
__device__ __align__(16) __half g_qh[(size_t)NODES_TOTAL * HIDF];  // 51.2 MB (L2-resident)
__device__ __align__(16) __half g_cat[(size_t)NNODES * CATF];      // 20.5 MB
__device__ __align__(16) __half g_qw16[INF * HIDF];                // Qw in fp16
__device__ __align__(16) __half g_ww16[OUTF * CATF];               // Ww in fp16

// ---------------------------------------------------------------------------
// helpers
// ---------------------------------------------------------------------------
__device__ __forceinline__ void mma_f16_f32acc(float c[4], const uint32_t a[4],
                                               uint32_t b0, uint32_t b1) {
    asm volatile("mma.sync.aligned.m16n8k16.row.col.f32.f16.f16.f32 "
                 "{%0,%1,%2,%3}, {%4,%5,%6,%7}, {%8,%9}, {%0,%1,%2,%3};"
                 : "+f"(c[0]), "+f"(c[1]), "+f"(c[2]), "+f"(c[3])
                 : "r"(a[0]), "r"(a[1]), "r"(a[2]), "r"(a[3]), "r"(b0), "r"(b1));
}

__device__ __forceinline__ void ldmatrix_x4(uint32_t r[4], uint32_t saddr) {
    asm volatile("ldmatrix.sync.aligned.m8n8.x4.shared.b16 {%0,%1,%2,%3}, [%4];"
                 : "=r"(r[0]), "=r"(r[1]), "=r"(r[2]), "=r"(r[3]) : "r"(saddr));
}

__device__ __forceinline__ uint32_t pack_h2(float x, float y) {
    __half2 h = __float22half2_rn(make_float2(x, y));
    return *(uint32_t*)&h;
}

__device__ __forceinline__ void cp_async16(void* smem_dst, const void* gmem_src, bool pred) {
    uint32_t saddr = (uint32_t)__cvta_generic_to_shared(smem_dst);
    int sz = pred ? 16 : 0;
    asm volatile("cp.async.cg.shared.global [%0], [%1], 16, %2;"
                 :: "r"(saddr), "l"(gmem_src), "r"(sz));
}
#define CP_COMMIT() asm volatile("cp.async.commit_group;")
#define CP_WAIT0()  asm volatile("cp.async.wait_group 0;")

#define SROWH 40   // smem row stride in halves (80B -> conflict-free ldmatrix)

// ---------------------------------------------------------------------------
// k0: one-shot weight conversion fp32 -> fp16 (identical RN rounding to the
// per-stage conversion previously done inside the GEMMs).
// Qw: 65536 floats (16384 float4), Ww: 131072 floats (32768 float4).
// ---------------------------------------------------------------------------
__global__ __launch_bounds__(256) void cvt_weights_kernel(
    const float* __restrict__ Qw, const float* __restrict__ Ww)
{
    const int i = blockIdx.x * 256 + threadIdx.x;
    if (i < 16384) {
        const float4 v = ((const float4*)Qw)[i];
        ((uint2*)g_qw16)[i] = make_uint2(pack_h2(v.x, v.y), pack_h2(v.z, v.w));
    } else if (i < 49152) {
        const int j = i - 16384;
        const float4 v = ((const float4*)Ww)[j];
        ((uint2*)g_ww16)[j] = make_uint2(pack_h2(v.x, v.y), pack_h2(v.z, v.w));
    }
}

// ===========================================================================
// GEMM-A: QH[m, n0..+127] = relu( h @ Qw^T + Qb ), fp16 out.  K=256.
// A fp32 (register prefetch + cvt at STS), B fp16 via cp.async double buffer.
// CTA tile 128x128, 8 warps (64x32). One __syncthreads per chunk.
// Grid.x = tileM*2 + colTile (colTile fastest: A slab L2-hot on 2nd N-tile).
// ===========================================================================
__global__ __launch_bounds__(256, 2) void gemm_a_kernel(
    const float* __restrict__ A, const __half* __restrict__ B,
    const float* __restrict__ bias, __half* __restrict__ C, int M)
{
    __shared__ __half sA[2][128 * SROWH];
    __shared__ __half sB[2][128 * SROWH];

    const int tid  = threadIdx.x;
    const int warp = tid >> 5;
    const int lane = tid & 31;
    const int g    = lane >> 2;
    const int tg   = lane & 3;
    const int m0   = (int)(blockIdx.x >> 1) * 128;
    const int n0   = (int)(blockIdx.x & 1) * 128;
    const int wm   = (warp >> 2) * 64;
    const int wn   = (warp & 3) * 32;

    // A staging: thread owns row tid>>1, 16-float slot (tid&1)*16
    const int srow = tid >> 1;
    const int part = (tid & 1) * 16;
    const bool va  = (m0 + srow) < M;
    // B cp.async tasks: i in {tid, tid+256}: row i>>2, 8-half granule (i&3)*8
    const int br0 = tid >> 2,         bg0 = (tid & 3) * 8;
    const int br1 = (tid + 256) >> 2, bg1 = ((tid + 256) & 3) * 8;

    float acc[4][4][4];
    #pragma unroll
    for (int i = 0; i < 4; i++)
        #pragma unroll
        for (int j = 0; j < 4; j++)
            #pragma unroll
            for (int r = 0; r < 4; r++) acc[i][j][r] = 0.f;

    // ---- prologue: stage chunk 0 ----
    #pragma unroll
    for (int i = 0; i < 4; i++) {
        const int kc = part + i * 4;
        float4 v = va ? *(const float4*)(A + (size_t)(m0 + srow) * 256 + kc)
                      : make_float4(0.f, 0.f, 0.f, 0.f);
        *(uint2*)&sA[0][srow * SROWH + kc] =
            make_uint2(pack_h2(v.x, v.y), pack_h2(v.z, v.w));
    }
    cp_async16(&sB[0][br0 * SROWH + bg0], B + (size_t)(n0 + br0) * 256 + bg0, true);
    cp_async16(&sB[0][br1 * SROWH + bg1], B + (size_t)(n0 + br1) * 256 + bg1, true);
    CP_COMMIT();
    CP_WAIT0();
    __syncthreads();

    const uint32_t uA0 = (uint32_t)__cvta_generic_to_shared(&sA[0][0]);
    const uint32_t uA1 = (uint32_t)__cvta_generic_to_shared(&sA[1][0]);
    const uint32_t uB0 = (uint32_t)__cvta_generic_to_shared(&sB[0][0]);
    const uint32_t uB1 = (uint32_t)__cvta_generic_to_shared(&sB[1][0]);
    const uint32_t offA = (uint32_t)(((lane & 15) * SROWH + (lane >> 4) * 8) * 2);
    const uint32_t offB = (uint32_t)((((lane >> 4) * 8 + (lane & 7)) * SROWH
                                      + ((lane >> 3) & 1) * 8) * 2);

    #pragma unroll 1
    for (int c = 0; c < 8; c++) {
        // ---- async-stage B chunk c+1, reg-prefetch A chunk c+1 ----
        float4 pa[4];
        if (c < 7) {
            const int kk = (c + 1) * 32;
            __half* dB = ((c + 1) & 1) ? &sB[1][0] : &sB[0][0];
            cp_async16(&dB[br0 * SROWH + bg0], B + (size_t)(n0 + br0) * 256 + kk + bg0, true);
            cp_async16(&dB[br1 * SROWH + bg1], B + (size_t)(n0 + br1) * 256 + kk + bg1, true);
            CP_COMMIT();
            #pragma unroll
            for (int i = 0; i < 4; i++)
                pa[i] = va ? *(const float4*)(A + (size_t)(m0 + srow) * 256 + kk + part + i * 4)
                           : make_float4(0.f, 0.f, 0.f, 0.f);
        }

        // ---- compute chunk c ----
        const uint32_t ubA = (c & 1) ? uA1 : uA0;
        const uint32_t ubB = (c & 1) ? uB1 : uB0;
        #pragma unroll
        for (int ks = 0; ks < 2; ks++) {
            uint32_t af[4][4];
            #pragma unroll
            for (int mf = 0; mf < 4; mf++)
                ldmatrix_x4(af[mf], ubA + offA
                            + (uint32_t)(((wm + mf * 16) * SROWH + ks * 16) * 2));
            uint32_t bf[2][4];
            #pragma unroll
            for (int p = 0; p < 2; p++)
                ldmatrix_x4(bf[p], ubB + offB
                            + (uint32_t)(((wn + p * 16) * SROWH + ks * 16) * 2));
            #pragma unroll
            for (int mf = 0; mf < 4; mf++)
                #pragma unroll
                for (int nf = 0; nf < 4; nf++)
                    mma_f16_f32acc(acc[mf][nf], af[mf], bf[nf >> 1][(nf & 1) * 2],
                                   bf[nf >> 1][(nf & 1) * 2 + 1]);
        }

        // ---- store prefetched A chunk c+1; await B copies; swap ----
        if (c < 7) {
            __half* dA = ((c + 1) & 1) ? &sA[1][0] : &sA[0][0];
            #pragma unroll
            for (int i = 0; i < 4; i++)
                *(uint2*)&dA[srow * SROWH + part + i * 4] =
                    make_uint2(pack_h2(pa[i].x, pa[i].y), pack_h2(pa[i].z, pa[i].w));
            CP_WAIT0();
        }
        __syncthreads();
    }

    // ---- epilogue: bias + relu, fp16 store (row stride 256) ----
    #pragma unroll
    for (int mf = 0; mf < 4; mf++) {
        #pragma unroll
        for (int half = 0; half < 2; half++) {
            const int m = m0 + wm + mf * 16 + g + half * 8;
            if (m < M) {
                #pragma unroll
                for (int nf = 0; nf < 4; nf++) {
                    const int cc = n0 + wn + nf * 8 + tg * 2;
                    const float v0 = fmaxf(acc[mf][nf][half * 2 + 0] + __ldg(&bias[cc]),     0.f);
                    const float v1 = fmaxf(acc[mf][nf][half * 2 + 1] + __ldg(&bias[cc + 1]), 0.f);
                    const uint32_t p = pack_h2(v0, v1);
                    *(uint32_t*)(C + (size_t)m * 256 + cc) = p;
                }
            }
        }
    }
}

// ===========================================================================
// GEMM-C: out[m, n0..+127] = relu( g_cat @ Ww^T + Wb ), fp32 out.  K=512.
// BOTH operands fp16 in gmem -> pure cp.async double-buffer pipeline,
// zero staging registers, zero conversions in the loop.
// ===========================================================================
__global__ __launch_bounds__(256, 2) void gemm_c_kernel(
    const __half* __restrict__ A, const __half* __restrict__ B,
    const float* __restrict__ bias, float* __restrict__ C, int M)
{
    __shared__ __half sA[2][128 * SROWH];
    __shared__ __half sB[2][128 * SROWH];

    const int tid  = threadIdx.x;
    const int warp = tid >> 5;
    const int lane = tid & 31;
    const int g    = lane >> 2;
    const int tg   = lane & 3;
    const int m0   = (int)(blockIdx.x >> 1) * 128;
    const int n0   = (int)(blockIdx.x & 1) * 128;
    const int wm   = (warp >> 2) * 64;
    const int wn   = (warp & 3) * 32;
    const int K    = 512;

    const int r0 = tid >> 2,         g0 = (tid & 3) * 8;
    const int r1 = (tid + 256) >> 2, g1 = ((tid + 256) & 3) * 8;
    const bool va0 = (m0 + r0) < M;
    const bool va1 = (m0 + r1) < M;

    float acc[4][4][4];
    #pragma unroll
    for (int i = 0; i < 4; i++)
        #pragma unroll
        for (int j = 0; j < 4; j++)
            #pragma unroll
            for (int r = 0; r < 4; r++) acc[i][j][r] = 0.f;

    // ---- prologue: async-stage chunk 0 ----
    cp_async16(&sA[0][r0 * SROWH + g0], A + (size_t)(m0 + r0) * K + g0, va0);
    cp_async16(&sA[0][r1 * SROWH + g1], A + (size_t)(m0 + r1) * K + g1, va1);
    cp_async16(&sB[0][r0 * SROWH + g0], B + (size_t)(n0 + r0) * K + g0, true);
    cp_async16(&sB[0][r1 * SROWH + g1], B + (size_t)(n0 + r1) * K + g1, true);
    CP_COMMIT();
    CP_WAIT0();
    __syncthreads();

    const uint32_t uA0 = (uint32_t)__cvta_generic_to_shared(&sA[0][0]);
    const uint32_t uA1 = (uint32_t)__cvta_generic_to_shared(&sA[1][0]);
    const uint32_t uB0 = (uint32_t)__cvta_generic_to_shared(&sB[0][0]);
    const uint32_t uB1 = (uint32_t)__cvta_generic_to_shared(&sB[1][0]);
    const uint32_t offA = (uint32_t)(((lane & 15) * SROWH + (lane >> 4) * 8) * 2);
    const uint32_t offB = (uint32_t)((((lane >> 4) * 8 + (lane & 7)) * SROWH
                                      + ((lane >> 3) & 1) * 8) * 2);

    #pragma unroll 1
    for (int c = 0; c < 16; c++) {
        if (c < 15) {
            const int kk = (c + 1) * 32;
            __half* dA = ((c + 1) & 1) ? &sA[1][0] : &sA[0][0];
            __half* dB = ((c + 1) & 1) ? &sB[1][0] : &sB[0][0];
            cp_async16(&dA[r0 * SROWH + g0], A + (size_t)(m0 + r0) * K + kk + g0, va0);
            cp_async16(&dA[r1 * SROWH + g1], A + (size_t)(m0 + r1) * K + kk + g1, va1);
            cp_async16(&dB[r0 * SROWH + g0], B + (size_t)(n0 + r0) * K + kk + g0, true);
            cp_async16(&dB[r1 * SROWH + g1], B + (size_t)(n0 + r1) * K + kk + g1, true);
            CP_COMMIT();
        }

        const uint32_t ubA = (c & 1) ? uA1 : uA0;
        const uint32_t ubB = (c & 1) ? uB1 : uB0;
        #pragma unroll
        for (int ks = 0; ks < 2; ks++) {
            uint32_t af[4][4];
            #pragma unroll
            for (int mf = 0; mf < 4; mf++)
                ldmatrix_x4(af[mf], ubA + offA
                            + (uint32_t)(((wm + mf * 16) * SROWH + ks * 16) * 2));
            uint32_t bf[2][4];
            #pragma unroll
            for (int p = 0; p < 2; p++)
                ldmatrix_x4(bf[p], ubB + offB
                            + (uint32_t)(((wn + p * 16) * SROWH + ks * 16) * 2));
            #pragma unroll
            for (int mf = 0; mf < 4; mf++)
                #pragma unroll
                for (int nf = 0; nf < 4; nf++)
                    mma_f16_f32acc(acc[mf][nf], af[mf], bf[nf >> 1][(nf & 1) * 2],
                                   bf[nf >> 1][(nf & 1) * 2 + 1]);
        }

        if (c < 15) CP_WAIT0();
        __syncthreads();
    }

    // ---- epilogue: bias + relu, fp32 store (row stride 256) ----
    #pragma unroll
    for (int mf = 0; mf < 4; mf++) {
        #pragma unroll
        for (int half = 0; half < 2; half++) {
            const int m = m0 + wm + mf * 16 + g + half * 8;
            if (m < M) {
                #pragma unroll
                for (int nf = 0; nf < 4; nf++) {
                    const int cc = n0 + wn + nf * 8 + tg * 2;
                    const float v0 = fmaxf(acc[mf][nf][half * 2 + 0] + __ldg(&bias[cc]),     0.f);
                    const float v1 = fmaxf(acc[mf][nf][half * 2 + 1] + __ldg(&bias[cc + 1]), 0.f);
                    *(float2*)(C + (size_t)m * 256 + cc) = make_float2(v0, v1);
                }
            }
        }
    }
}

// ---------------------------------------------------------------------------
// Aggregation: h_agg[n] = sum_t w[n,t]*QH[nb[n,t]] / sum_t w[n,t]
// QH fp16 (L2-resident). One warp per node; also copies h[nodeset[n]]
// (fp32 -> fp16) into the first half of the fp16 concat row.
// ---------------------------------------------------------------------------
__global__ __launch_bounds__(256) void agg_kernel(
    const float* __restrict__ h, const int* __restrict__ nodeset,
    const int* __restrict__ nb_nodes, const float* __restrict__ nb_w)
{
    __shared__ int   s_idx[8][TN];
    __shared__ float s_w[8][TN];

    const int tid  = threadIdx.x;
    const int warp = tid >> 5;
    const int lane = tid & 31;
    const int n    = blockIdx.x * 8 + warp;   // 20000/8 = 2500 blocks exact

    for (int j = lane; j < TN; j += 32) {
        s_idx[warp][j] = nb_nodes[n * TN + j];
        s_w[warp][j]   = nb_w[n * TN + j];
    }
    __syncwarp();

    float wsum = 0.f;
    #pragma unroll
    for (int t = 0; t < TN; t++) wsum += s_w[warp][t];   // smem broadcast

    const int colb = lane * 8;
    float acc[8];
    #pragma unroll
    for (int i = 0; i < 8; i++) acc[i] = 0.f;

    #pragma unroll 10
    for (int t = 0; t < TN; t++) {
        const int   idx = s_idx[warp][t];
        const float w   = s_w[warp][t];
        union { uint4 u; __half2 h2[4]; } q;
        q.u = *(const uint4*)(g_qh + (size_t)idx * HIDF + colb);
        #pragma unroll
        for (int i = 0; i < 4; i++) {
            const float2 f = __half22float2(q.h2[i]);
            acc[2 * i]     += w * f.x;
            acc[2 * i + 1] += w * f.y;
        }
    }
    const float inv = 1.f / wsum;
    union { uint4 u; __half2 h2[4]; } o;
    #pragma unroll
    for (int i = 0; i < 4; i++)
        o.h2[i] = __float22half2_rn(make_float2(acc[2 * i] * inv, acc[2 * i + 1] * inv));
    *(uint4*)(g_cat + (size_t)n * CATF + INF + colb) = o.u;

    const int self = nodeset[n];
    const float4 s0 = *(const float4*)(h + (size_t)self * INF + colb);
    const float4 s1 = *(const float4*)(h + (size_t)self * INF + colb + 4);
    union { uint4 u; __half2 h2[4]; } sc;
    sc.h2[0] = __float22half2_rn(make_float2(s0.x, s0.y));
    sc.h2[1] = __float22half2_rn(make_float2(s0.z, s0.w));
    sc.h2[2] = __float22half2_rn(make_float2(s1.x, s1.y));
    sc.h2[3] = __float22half2_rn(make_float2(s1.z, s1.w));
    *(uint4*)(g_cat + (size_t)n * CATF + colb) = sc.u;
}

// ---------------------------------------------------------------------------
// In-place row L2 normalize of d_out [20000, 256]; one warp per row
// ---------------------------------------------------------------------------
__global__ __launch_bounds__(256) void norm_kernel(float* __restrict__ out)
{
    const int gwarp = (blockIdx.x * blockDim.x + threadIdx.x) >> 5;
    const int lane  = threadIdx.x & 31;
    if (gwarp >= NNODES) return;
    float* row = out + (size_t)gwarp * OUTF;

    float4 v0 = *(float4*)&row[lane * 4];
    float4 v1 = *(float4*)&row[128 + lane * 4];
    float ss = v0.x * v0.x + v0.y * v0.y + v0.z * v0.z + v0.w * v0.w
             + v1.x * v1.x + v1.y * v1.y + v1.z * v1.z + v1.w * v1.w;
    #pragma unroll
    for (int o = 16; o; o >>= 1) ss += __shfl_xor_sync(0xffffffffu, ss, o);
    const float inv = rsqrtf(ss);
    v0.x *= inv; v0.y *= inv; v0.z *= inv; v0.w *= inv;
    v1.x *= inv; v1.y *= inv; v1.z *= inv; v1.w *= inv;
    *(float4*)&row[lane * 4]       = v0;
    *(float4*)&row[128 + lane * 4] = v1;
}

// ---------------------------------------------------------------------------
extern "C" void kernel_launch(void* const* d_in, const int* in_sizes, int n_in,
                              void* d_out, int out_size)
{
    const float* h        = (const float*)d_in[0];
    const int*   nodeset  = (const int*)d_in[1];
    const int*   nb_nodes = (const int*)d_in[2];
    const float* nb_w     = (const float*)d_in[3];
    const float* Qw       = (const float*)d_in[4];
    const float* Qb       = (const float*)d_in[5];
    const float* Ww       = (const float*)d_in[6];
    const float* Wb       = (const float*)d_in[7];
    float*       out      = (float*)d_out;

    __half* qh   = nullptr;
    __half* cat  = nullptr;
    __half* qw16 = nullptr;
    __half* ww16 = nullptr;
    cudaGetSymbolAddress((void**)&qh,   g_qh);
    cudaGetSymbolAddress((void**)&cat,  g_cat);
    cudaGetSymbolAddress((void**)&qw16, g_qw16);
    cudaGetSymbolAddress((void**)&ww16, g_ww16);

    // k0: weights -> fp16 (once per launch; ~2us)
    cvt_weights_kernel<<<192, 256>>>(Qw, Ww);

    // k1: QH = relu(h @ Qw^T + Qb) -> fp16 [100000, 256]
    {
        const int tilesM = (NODES_TOTAL + 127) / 128;   // 782
        gemm_a_kernel<<<tilesM * 2, 256>>>(h, qw16, Qb, qh, NODES_TOTAL);
    }
    // k2: aggregate + self gather -> g_cat fp16 [20000, 512]
    agg_kernel<<<NNODES / 8, 256>>>(h, nodeset, nb_nodes, nb_w);

    // k3: out = relu(g_cat @ Ww^T + Wb)  [20000, 256], K=512
    {
        const int tilesM = (NNODES + 127) / 128;        // 157
        gemm_c_kernel<<<tilesM * 2, 256>>>(cat, ww16, Wb, out, NNODES);
    }
    // k4: in-place L2 normalize
    norm_kernel<<<(NNODES * 32 + 255) / 256, 256>>>(out);
}

// round 13
// speedup vs baseline: 2.3001x; 1.0578x over previous
#include <cuda_runtime.h>
#include <cuda_fp16.h>
#include <cstdint>

#define NODES_TOTAL 100000
#define NNODES      20000
#define TN          50
#define INF         256
#define HIDF        256
#define OUTF        256
#define CATF        512

// Scratch (static __device__ arrays: allocation-free per harness rules)
__device__ __align__(16) __half g_qh[(size_t)NODES_TOTAL * HIDF];  // 51.2 MB (L2-resident)
__device__ __align__(16) __half g_cat[(size_t)NNODES * CATF];      // 20.5 MB
__device__ __align__(16) __half g_qw16[INF * HIDF];                // Qw in fp16
__device__ __align__(16) __half g_ww16[OUTF * CATF];               // Ww in fp16

// ---------------------------------------------------------------------------
// helpers
// ---------------------------------------------------------------------------
__device__ __forceinline__ void mma_f16_f32acc(float c[4], const uint32_t a[4],
                                               uint32_t b0, uint32_t b1) {
    asm volatile("mma.sync.aligned.m16n8k16.row.col.f32.f16.f16.f32 "
                 "{%0,%1,%2,%3}, {%4,%5,%6,%7}, {%8,%9}, {%0,%1,%2,%3};"
                 : "+f"(c[0]), "+f"(c[1]), "+f"(c[2]), "+f"(c[3])
                 : "r"(a[0]), "r"(a[1]), "r"(a[2]), "r"(a[3]), "r"(b0), "r"(b1));
}

__device__ __forceinline__ void ldmatrix_x4(uint32_t r[4], uint32_t saddr) {
    asm volatile("ldmatrix.sync.aligned.m8n8.x4.shared.b16 {%0,%1,%2,%3}, [%4];"
                 : "=r"(r[0]), "=r"(r[1]), "=r"(r[2]), "=r"(r[3]) : "r"(saddr));
}

__device__ __forceinline__ uint32_t pack_h2(float x, float y) {
    __half2 h = __float22half2_rn(make_float2(x, y));
    return *(uint32_t*)&h;
}

__device__ __forceinline__ void cp_async16(void* smem_dst, const void* gmem_src, bool pred) {
    uint32_t saddr = (uint32_t)__cvta_generic_to_shared(smem_dst);
    int sz = pred ? 16 : 0;
    asm volatile("cp.async.cg.shared.global [%0], [%1], 16, %2;"
                 :: "r"(saddr), "l"(gmem_src), "r"(sz));
}
#define CP_COMMIT() asm volatile("cp.async.commit_group;")
#define CP_WAIT0()  asm volatile("cp.async.wait_group 0;")

#define SROWH 40   // smem row stride in halves (80B -> conflict-free ldmatrix)

// ---------------------------------------------------------------------------
// k0: one-shot weight conversion fp32 -> fp16 (identical RN rounding to the
// previous in-GEMM conversion).
// ---------------------------------------------------------------------------
__global__ __launch_bounds__(256) void cvt_weights_kernel(
    const float* __restrict__ Qw, const float* __restrict__ Ww)
{
    const int i = blockIdx.x * 256 + threadIdx.x;
    if (i < 16384) {
        const float4 v = ((const float4*)Qw)[i];
        ((uint2*)g_qw16)[i] = make_uint2(pack_h2(v.x, v.y), pack_h2(v.z, v.w));
    } else if (i < 49152) {
        const int j = i - 16384;
        const float4 v = ((const float4*)Ww)[j];
        ((uint2*)g_ww16)[j] = make_uint2(pack_h2(v.x, v.y), pack_h2(v.z, v.w));
    }
}

// ===========================================================================
// GEMM-A: QH[m0..m0+63, 0..255] = relu( h @ Qw^T + Qb ), fp16 out. K=256.
// CTA tile 64(M) x 256(N) — FULL N per CTA: each A slab is read from DRAM
// exactly once (was ~1.5x with the N-pair scheme). 8 warps of 32x64.
// A fp32: register prefetch (8 regs) + cvt at STS. B fp16: cp.async
// double-buffered 32-wide K chunks. One __syncthreads per chunk.
// Dynamic smem 51200 B -> 2 CTAs/SM.
// ===========================================================================
#define GEMM_A_SMEM ((2 * 64 * SROWH + 2 * 256 * SROWH) * 2)   // 51200 B

__global__ __launch_bounds__(256, 2) void gemm_a_kernel(
    const float* __restrict__ A, const __half* __restrict__ B,
    const float* __restrict__ bias, __half* __restrict__ C, int M)
{
    extern __shared__ __half dsm[];
    __half* sA0 = dsm;                       // 64 x SROWH
    __half* sA1 = dsm + 64 * SROWH;
    __half* sB0 = dsm + 2 * 64 * SROWH;      // 256 x SROWH
    __half* sB1 = sB0 + 256 * SROWH;

    const int tid  = threadIdx.x;
    const int warp = tid >> 5;
    const int lane = tid & 31;
    const int g    = lane >> 2;
    const int tg   = lane & 3;
    const int m0   = (int)blockIdx.x * 64;
    const int wm   = (warp >> 2) * 32;   // 2 M groups
    const int wn   = (warp & 3) * 64;    // 4 N groups of 64

    // A staging: 64 rows x 32 floats; thread owns row tid>>2, 8 floats at (tid&3)*8
    const int arow = tid >> 2;
    const int acol = (tid & 3) * 8;
    const bool va  = (m0 + arow) < M;
    // B staging: 256 rows x 32 halves = 1024 16B-granules; 4 tasks/thread
    // task i = tid + t*256: row i>>2, granule (i&3)*8 halves

    float acc[2][8][4];
    #pragma unroll
    for (int i = 0; i < 2; i++)
        #pragma unroll
        for (int j = 0; j < 8; j++)
            #pragma unroll
            for (int r = 0; r < 4; r++) acc[i][j][r] = 0.f;

    // ---- prologue: stage chunk 0 ----
    #pragma unroll
    for (int t = 0; t < 4; t++) {
        const int i  = tid + t * 256;
        const int br = i >> 2, bg = (i & 3) * 8;
        cp_async16(&sB0[br * SROWH + bg], B + (size_t)br * 256 + bg, true);
    }
    CP_COMMIT();
    {
        float4 v0 = va ? *(const float4*)(A + (size_t)(m0 + arow) * 256 + acol)
                       : make_float4(0.f, 0.f, 0.f, 0.f);
        float4 v1 = va ? *(const float4*)(A + (size_t)(m0 + arow) * 256 + acol + 4)
                       : make_float4(0.f, 0.f, 0.f, 0.f);
        *(uint4*)&sA0[arow * SROWH + acol] =
            make_uint4(pack_h2(v0.x, v0.y), pack_h2(v0.z, v0.w),
                       pack_h2(v1.x, v1.y), pack_h2(v1.z, v1.w));
    }
    CP_WAIT0();
    __syncthreads();

    const uint32_t uA0 = (uint32_t)__cvta_generic_to_shared(sA0);
    const uint32_t uA1 = (uint32_t)__cvta_generic_to_shared(sA1);
    const uint32_t uB0 = (uint32_t)__cvta_generic_to_shared(sB0);
    const uint32_t uB1 = (uint32_t)__cvta_generic_to_shared(sB1);
    const uint32_t offA = (uint32_t)(((lane & 15) * SROWH + (lane >> 4) * 8) * 2);
    const uint32_t offB = (uint32_t)((((lane >> 4) * 8 + (lane & 7)) * SROWH
                                      + ((lane >> 3) & 1) * 8) * 2);

    #pragma unroll 1
    for (int c = 0; c < 8; c++) {
        // ---- async-stage B chunk c+1; reg-prefetch A chunk c+1 ----
        float4 pa0, pa1;
        if (c < 7) {
            const int kk = (c + 1) * 32;
            __half* dB = ((c + 1) & 1) ? sB1 : sB0;
            #pragma unroll
            for (int t = 0; t < 4; t++) {
                const int i  = tid + t * 256;
                const int br = i >> 2, bg = (i & 3) * 8;
                cp_async16(&dB[br * SROWH + bg], B + (size_t)br * 256 + kk + bg, true);
            }
            CP_COMMIT();
            pa0 = va ? *(const float4*)(A + (size_t)(m0 + arow) * 256 + kk + acol)
                     : make_float4(0.f, 0.f, 0.f, 0.f);
            pa1 = va ? *(const float4*)(A + (size_t)(m0 + arow) * 256 + kk + acol + 4)
                     : make_float4(0.f, 0.f, 0.f, 0.f);
        }

        // ---- compute chunk c ----
        const uint32_t ubA = (c & 1) ? uA1 : uA0;
        const uint32_t ubB = (c & 1) ? uB1 : uB0;
        #pragma unroll
        for (int ks = 0; ks < 2; ks++) {
            uint32_t af[2][4];
            #pragma unroll
            for (int mf = 0; mf < 2; mf++)
                ldmatrix_x4(af[mf], ubA + offA
                            + (uint32_t)(((wm + mf * 16) * SROWH + ks * 16) * 2));
            uint32_t bf[4][4];
            #pragma unroll
            for (int p = 0; p < 4; p++)
                ldmatrix_x4(bf[p], ubB + offB
                            + (uint32_t)(((wn + p * 16) * SROWH + ks * 16) * 2));
            #pragma unroll
            for (int mf = 0; mf < 2; mf++)
                #pragma unroll
                for (int nf = 0; nf < 8; nf++)
                    mma_f16_f32acc(acc[mf][nf], af[mf], bf[nf >> 1][(nf & 1) * 2],
                                   bf[nf >> 1][(nf & 1) * 2 + 1]);
        }

        // ---- store prefetched A; await B copies; swap ----
        if (c < 7) {
            __half* dA = ((c + 1) & 1) ? sA1 : sA0;
            *(uint4*)&dA[arow * SROWH + acol] =
                make_uint4(pack_h2(pa0.x, pa0.y), pack_h2(pa0.z, pa0.w),
                           pack_h2(pa1.x, pa1.y), pack_h2(pa1.z, pa1.w));
            CP_WAIT0();
        }
        __syncthreads();
    }

    // ---- epilogue: bias + relu, fp16 store (row stride 256) ----
    #pragma unroll
    for (int mf = 0; mf < 2; mf++) {
        #pragma unroll
        for (int half = 0; half < 2; half++) {
            const int m = m0 + wm + mf * 16 + g + half * 8;
            if (m < M) {
                #pragma unroll
                for (int nf = 0; nf < 8; nf++) {
                    const int cc = wn + nf * 8 + tg * 2;
                    const float v0 = fmaxf(acc[mf][nf][half * 2 + 0] + __ldg(&bias[cc]),     0.f);
                    const float v1 = fmaxf(acc[mf][nf][half * 2 + 1] + __ldg(&bias[cc + 1]), 0.f);
                    *(uint32_t*)(C + (size_t)m * 256 + cc) = pack_h2(v0, v1);
                }
            }
        }
    }
}

// ===========================================================================
// GEMM-C: out[m0..m0+63, n0..n0+127] = relu( g_cat @ Ww^T + Wb ), fp32 out.
// K=512, both operands fp16 -> pure cp.async double buffer.
// CTA tile 64x128 (8 warps of 32x32): 626 CTAs, ~80 regs, 30.7 KB smem ->
// 3 CTAs/SM and 1.41 waves (fixes the 2-wave tail of the 128x128 version).
// ===========================================================================
__global__ __launch_bounds__(256, 3) void gemm_c_kernel(
    const __half* __restrict__ A, const __half* __restrict__ B,
    const float* __restrict__ bias, float* __restrict__ C, int M)
{
    __shared__ __half sA[2][64 * SROWH];
    __shared__ __half sB[2][128 * SROWH];

    const int tid  = threadIdx.x;
    const int warp = tid >> 5;
    const int lane = tid & 31;
    const int g    = lane >> 2;
    const int tg   = lane & 3;
    const int m0   = (int)(blockIdx.x >> 1) * 64;
    const int n0   = (int)(blockIdx.x & 1) * 128;
    const int wm   = (warp >> 2) * 32;
    const int wn   = (warp & 3) * 32;
    const int K    = 512;

    // A: 64 rows x 32 halves = 256 granules -> 1 task/thread
    const int ar = tid >> 2, ag = (tid & 3) * 8;
    const bool va = (m0 + ar) < M;
    // B: 128 rows x 32 halves = 512 granules -> 2 tasks/thread
    const int br0 = tid >> 2,         bg0 = (tid & 3) * 8;
    const int br1 = (tid + 256) >> 2, bg1 = ((tid + 256) & 3) * 8;

    float acc[2][4][4];
    #pragma unroll
    for (int i = 0; i < 2; i++)
        #pragma unroll
        for (int j = 0; j < 4; j++)
            #pragma unroll
            for (int r = 0; r < 4; r++) acc[i][j][r] = 0.f;

    // ---- prologue: async-stage chunk 0 ----
    cp_async16(&sA[0][ar * SROWH + ag],  A + (size_t)(m0 + ar) * K + ag, va);
    cp_async16(&sB[0][br0 * SROWH + bg0], B + (size_t)(n0 + br0) * K + bg0, true);
    cp_async16(&sB[0][br1 * SROWH + bg1], B + (size_t)(n0 + br1) * K + bg1, true);
    CP_COMMIT();
    CP_WAIT0();
    __syncthreads();

    const uint32_t uA0 = (uint32_t)__cvta_generic_to_shared(&sA[0][0]);
    const uint32_t uA1 = (uint32_t)__cvta_generic_to_shared(&sA[1][0]);
    const uint32_t uB0 = (uint32_t)__cvta_generic_to_shared(&sB[0][0]);
    const uint32_t uB1 = (uint32_t)__cvta_generic_to_shared(&sB[1][0]);
    const uint32_t offA = (uint32_t)(((lane & 15) * SROWH + (lane >> 4) * 8) * 2);
    const uint32_t offB = (uint32_t)((((lane >> 4) * 8 + (lane & 7)) * SROWH
                                      + ((lane >> 3) & 1) * 8) * 2);

    #pragma unroll 1
    for (int c = 0; c < 16; c++) {
        if (c < 15) {
            const int kk = (c + 1) * 32;
            __half* dA = ((c + 1) & 1) ? &sA[1][0] : &sA[0][0];
            __half* dB = ((c + 1) & 1) ? &sB[1][0] : &sB[0][0];
            cp_async16(&dA[ar * SROWH + ag],  A + (size_t)(m0 + ar) * K + kk + ag, va);
            cp_async16(&dB[br0 * SROWH + bg0], B + (size_t)(n0 + br0) * K + kk + bg0, true);
            cp_async16(&dB[br1 * SROWH + bg1], B + (size_t)(n0 + br1) * K + kk + bg1, true);
            CP_COMMIT();
        }

        const uint32_t ubA = (c & 1) ? uA1 : uA0;
        const uint32_t ubB = (c & 1) ? uB1 : uB0;
        #pragma unroll
        for (int ks = 0; ks < 2; ks++) {
            uint32_t af[2][4];
            #pragma unroll
            for (int mf = 0; mf < 2; mf++)
                ldmatrix_x4(af[mf], ubA + offA
                            + (uint32_t)(((wm + mf * 16) * SROWH + ks * 16) * 2));
            uint32_t bf[2][4];
            #pragma unroll
            for (int p = 0; p < 2; p++)
                ldmatrix_x4(bf[p], ubB + offB
                            + (uint32_t)(((wn + p * 16) * SROWH + ks * 16) * 2));
            #pragma unroll
            for (int mf = 0; mf < 2; mf++)
                #pragma unroll
                for (int nf = 0; nf < 4; nf++)
                    mma_f16_f32acc(acc[mf][nf], af[mf], bf[nf >> 1][(nf & 1) * 2],
                                   bf[nf >> 1][(nf & 1) * 2 + 1]);
        }

        if (c < 15) CP_WAIT0();
        __syncthreads();
    }

    // ---- epilogue: bias + relu, fp32 store (row stride 256) ----
    #pragma unroll
    for (int mf = 0; mf < 2; mf++) {
        #pragma unroll
        for (int half = 0; half < 2; half++) {
            const int m = m0 + wm + mf * 16 + g + half * 8;
            if (m < M) {
                #pragma unroll
                for (int nf = 0; nf < 4; nf++) {
                    const int cc = n0 + wn + nf * 8 + tg * 2;
                    const float v0 = fmaxf(acc[mf][nf][half * 2 + 0] + __ldg(&bias[cc]),     0.f);
                    const float v1 = fmaxf(acc[mf][nf][half * 2 + 1] + __ldg(&bias[cc + 1]), 0.f);
                    *(float2*)(C + (size_t)m * 256 + cc) = make_float2(v0, v1);
                }
            }
        }
    }
}

// ---------------------------------------------------------------------------
// Aggregation: h_agg[n] = sum_t w[n,t]*QH[nb[n,t]] / sum_t w[n,t]
// QH fp16 (L2-resident; at the chip LTS gather floor). One warp per node;
// also copies h[nodeset[n]] (fp32->fp16) into the first half of g_cat row.
// ---------------------------------------------------------------------------
__global__ __launch_bounds__(256) void agg_kernel(
    const float* __restrict__ h, const int* __restrict__ nodeset,
    const int* __restrict__ nb_nodes, const float* __restrict__ nb_w)
{
    __shared__ int   s_idx[8][TN];
    __shared__ float s_w[8][TN];

    const int tid  = threadIdx.x;
    const int warp = tid >> 5;
    const int lane = tid & 31;
    const int n    = blockIdx.x * 8 + warp;   // 20000/8 = 2500 blocks exact

    for (int j = lane; j < TN; j += 32) {
        s_idx[warp][j] = nb_nodes[n * TN + j];
        s_w[warp][j]   = nb_w[n * TN + j];
    }
    __syncwarp();

    float wsum = 0.f;
    #pragma unroll
    for (int t = 0; t < TN; t++) wsum += s_w[warp][t];   // smem broadcast

    const int colb = lane * 8;
    float acc[8];
    #pragma unroll
    for (int i = 0; i < 8; i++) acc[i] = 0.f;

    #pragma unroll 10
    for (int t = 0; t < TN; t++) {
        const int   idx = s_idx[warp][t];
        const float w   = s_w[warp][t];
        union { uint4 u; __half2 h2[4]; } q;
        q.u = *(const uint4*)(g_qh + (size_t)idx * HIDF + colb);
        #pragma unroll
        for (int i = 0; i < 4; i++) {
            const float2 f = __half22float2(q.h2[i]);
            acc[2 * i]     += w * f.x;
            acc[2 * i + 1] += w * f.y;
        }
    }
    const float inv = 1.f / wsum;
    union { uint4 u; __half2 h2[4]; } o;
    #pragma unroll
    for (int i = 0; i < 4; i++)
        o.h2[i] = __float22half2_rn(make_float2(acc[2 * i] * inv, acc[2 * i + 1] * inv));
    *(uint4*)(g_cat + (size_t)n * CATF + INF + colb) = o.u;

    const int self = nodeset[n];
    const float4 s0 = *(const float4*)(h + (size_t)self * INF + colb);
    const float4 s1 = *(const float4*)(h + (size_t)self * INF + colb + 4);
    union { uint4 u; __half2 h2[4]; } sc;
    sc.h2[0] = __float22half2_rn(make_float2(s0.x, s0.y));
    sc.h2[1] = __float22half2_rn(make_float2(s0.z, s0.w));
    sc.h2[2] = __float22half2_rn(make_float2(s1.x, s1.y));
    sc.h2[3] = __float22half2_rn(make_float2(s1.z, s1.w));
    *(uint4*)(g_cat + (size_t)n * CATF + colb) = sc.u;
}

// ---------------------------------------------------------------------------
// In-place row L2 normalize of d_out [20000, 256]; one warp per row
// ---------------------------------------------------------------------------
__global__ __launch_bounds__(256) void norm_kernel(float* __restrict__ out)
{
    const int gwarp = (blockIdx.x * blockDim.x + threadIdx.x) >> 5;
    const int lane  = threadIdx.x & 31;
    if (gwarp >= NNODES) return;
    float* row = out + (size_t)gwarp * OUTF;

    float4 v0 = *(float4*)&row[lane * 4];
    float4 v1 = *(float4*)&row[128 + lane * 4];
    float ss = v0.x * v0.x + v0.y * v0.y + v0.z * v0.z + v0.w * v0.w
             + v1.x * v1.x + v1.y * v1.y + v1.z * v1.z + v1.w * v1.w;
    #pragma unroll
    for (int o = 16; o; o >>= 1) ss += __shfl_xor_sync(0xffffffffu, ss, o);
    const float inv = rsqrtf(ss);
    v0.x *= inv; v0.y *= inv; v0.z *= inv; v0.w *= inv;
    v1.x *= inv; v1.y *= inv; v1.z *= inv; v1.w *= inv;
    *(float4*)&row[lane * 4]       = v0;
    *(float4*)&row[128 + lane * 4] = v1;
}

// ---------------------------------------------------------------------------
extern "C" void kernel_launch(void* const* d_in, const int* in_sizes, int n_in,
                              void* d_out, int out_size)
{
    const float* h        = (const float*)d_in[0];
    const int*   nodeset  = (const int*)d_in[1];
    const int*   nb_nodes = (const int*)d_in[2];
    const float* nb_w     = (const float*)d_in[3];
    const float* Qw       = (const float*)d_in[4];
    const float* Qb       = (const float*)d_in[5];
    const float* Ww       = (const float*)d_in[6];
    const float* Wb       = (const float*)d_in[7];
    float*       out      = (float*)d_out;

    __half* qh   = nullptr;
    __half* cat  = nullptr;
    __half* qw16 = nullptr;
    __half* ww16 = nullptr;
    cudaGetSymbolAddress((void**)&qh,   g_qh);
    cudaGetSymbolAddress((void**)&cat,  g_cat);
    cudaGetSymbolAddress((void**)&qw16, g_qw16);
    cudaGetSymbolAddress((void**)&ww16, g_ww16);

    static bool attr_done = false;
    if (!attr_done) {
        cudaFuncSetAttribute(gemm_a_kernel,
                             cudaFuncAttributeMaxDynamicSharedMemorySize, GEMM_A_SMEM);
        attr_done = true;
    }

    // k0: weights -> fp16 (once per launch; ~2us)
    cvt_weights_kernel<<<192, 256>>>(Qw, Ww);

    // k1: QH = relu(h @ Qw^T + Qb) -> fp16 [100000, 256]
    {
        const int tilesM = (NODES_TOTAL + 63) / 64;   // 1563
        gemm_a_kernel<<<tilesM, 256, GEMM_A_SMEM>>>(h, qw16, Qb, qh, NODES_TOTAL);
    }
    // k2: aggregate + self gather -> g_cat fp16 [20000, 512]
    agg_kernel<<<NNODES / 8, 256>>>(h, nodeset, nb_nodes, nb_w);

    // k3: out = relu(g_cat @ Ww^T + Wb)  [20000, 256], K=512
    {
        const int tilesM = (NNODES + 63) / 64;        // 313
        gemm_c_kernel<<<tilesM * 2, 256>>>(cat, ww16, Wb, out, NNODES);
    }
    // k4: in-place L2 normalize
    norm_kernel<<<(NNODES * 32 + 255) / 256, 256>>>(out);
}